// round 13
// baseline (speedup 1.0000x reference)
#include <cuda_runtime.h>
#include <cuda_bf16.h>
#include <cstdint>
#include <cstddef>

#define B 4
#define T 2048
#define C 1024
#define H 64
#define NROW (B * T)
#define QSCALE 0.18033688011112042f   // 0.125 * log2(e)

// pre-split W (hi/lo bf16): rows 0-63 Wq, 64-127 Wk, 128-191 Wv
__device__ __align__(16) __nv_bfloat16 g_wh[192 * C];
__device__ __align__(16) __nv_bfloat16 g_wl[192 * C];
// projected q/k (bf16 hi/lo, [row][h]; q pre-scaled) and transposed v ([h][row])
__device__ __align__(16) __nv_bfloat16 g_qh[NROW * H];
__device__ __align__(16) __nv_bfloat16 g_ql[NROW * H];
__device__ __align__(16) __nv_bfloat16 g_kh[NROW * H];
__device__ __align__(16) __nv_bfloat16 g_kl[NROW * H];
__device__ __align__(16) __nv_bfloat16 g_vth[H * NROW];
__device__ __align__(16) __nv_bfloat16 g_vtl[H * NROW];
// split-K attention partials: [split][row][...]
__device__ float g_po[2 * NROW * H];
__device__ float g_pm[2 * NROW];
__device__ float g_pl[2 * NROW];

// ---------------------------------------------------------------------------
// Baseline-PTX helpers (sm_80+ only — no tcgen05 on this toolchain)
// ---------------------------------------------------------------------------
__device__ __forceinline__ uint32_t smem_u32(const void* p) {
    uint32_t a;
    asm("{ .reg .u64 t; cvta.to.shared.u64 t, %1; cvt.u32.u64 %0, t; }"
        : "=r"(a) : "l"(p));
    return a;
}
__device__ __forceinline__ void cp16(uint32_t dst, const void* src) {
    asm volatile("cp.async.cg.shared.global [%0], [%1], 16;"
                 :: "r"(dst), "l"(src) : "memory");
}
#define CP_COMMIT() asm volatile("cp.async.commit_group;" ::: "memory")
#define CP_WAIT1()  asm volatile("cp.async.wait_group 1;" ::: "memory")
#define CP_WAIT0()  asm volatile("cp.async.wait_group 0;" ::: "memory")
__device__ __forceinline__ void ldsm4(uint32_t* r, uint32_t addr) {
    asm volatile("ldmatrix.sync.aligned.m8n8.x4.shared.b16 {%0,%1,%2,%3}, [%4];"
                 : "=r"(r[0]), "=r"(r[1]), "=r"(r[2]), "=r"(r[3]) : "r"(addr));
}
__device__ __forceinline__ void mma_bf16(float* d, const uint32_t* a,
                                         const uint32_t* b) {
    asm volatile(
        "mma.sync.aligned.m16n8k16.row.col.f32.bf16.bf16.f32 "
        "{%0,%1,%2,%3}, {%4,%5,%6,%7}, {%8,%9}, {%0,%1,%2,%3};"
        : "+f"(d[0]), "+f"(d[1]), "+f"(d[2]), "+f"(d[3])
        : "r"(a[0]), "r"(a[1]), "r"(a[2]), "r"(a[3]), "r"(b[0]), "r"(b[1]));
}
__device__ __forceinline__ void split1(float v, __nv_bfloat16& h, __nv_bfloat16& l) {
    h = __float2bfloat16(v);
    l = __float2bfloat16(v - __bfloat162float(h));
}
__device__ __forceinline__ uint32_t bf2pack(__nv_bfloat16 lo, __nv_bfloat16 hi) {
    __nv_bfloat162 t{lo, hi};
    return *reinterpret_cast<uint32_t*>(&t);
}

// ---------------------------------------------------------------------------
// Kernel 0: split packed W into bf16 hi/lo (x is split inline in qkv_mma now)
// ---------------------------------------------------------------------------
#define W4 (192 * C / 4)

__global__ __launch_bounds__(256) void convert_w(const float* __restrict__ Wq,
                                                 const float* __restrict__ Wk,
                                                 const float* __restrict__ Wv) {
    int i = blockIdx.x * 256 + threadIdx.x;
    if (i >= W4) return;
    int wrow = i >> 8;            // 0..191
    int c4 = i & 255;
    const float* src = (wrow < 64)  ? Wq + (size_t)wrow * C
                     : (wrow < 128) ? Wk + (size_t)(wrow - 64) * C
                                    : Wv + (size_t)(wrow - 128) * C;
    float4 v = ((const float4*)src)[c4];
    const float a[4] = {v.x, v.y, v.z, v.w};
    __nv_bfloat16 h[4], l[4];
#pragma unroll
    for (int j = 0; j < 4; j++) split1(a[j], h[j], l[j]);
    size_t off = (size_t)wrow * C + (size_t)c4 * 4;
    __nv_bfloat162* ph = (__nv_bfloat162*)(g_wh + off);
    __nv_bfloat162* pl = (__nv_bfloat162*)(g_wl + off);
    ph[0] = {h[0], h[1]}; ph[1] = {h[2], h[3]};
    pl[0] = {l[0], l[1]}; pl[1] = {l[2], l[3]};
}

// ---------------------------------------------------------------------------
// Kernel 1: QKV projection on HMMA, fused x split.
// grid = 128 CTAs (M-tiles of 64 rows), N=192 (q|k|v), 256 threads = 8 warps
// (4m x 2n; warp tile m16 x n96). K chunks of 64, double-buffered:
// x fp32 via LDG -> in-register hi/lo split -> STS; W hi/lo via cp.async.
// ---------------------------------------------------------------------------
#define ASTR 72
#define AH_E 0
#define AL_E 4608          // 64*72
#define BH_E 9216
#define BL_E 23040         // +192*72
#define STG 36864          // bf16 elems per stage
#define PROJ_SMEM (2 * STG * 2)   // 147456 bytes

__global__ __launch_bounds__(256, 1) void qkv_mma(const float* __restrict__ x) {
    extern __shared__ __nv_bfloat16 smb[];
    char* sc = (char*)smb;
    const uint32_t su = smem_u32(smb);
    const int tid = threadIdx.x;
    const int lane = tid & 31;
    const int wid = tid >> 5;
    const int wm = wid & 3;        // m block: rows wm*16..wm*16+15
    const int wn = wid >> 2;       // n block: cols wn*96..wn*96+95
    const int rowBase = blockIdx.x * 64;

    const uint32_t aoff = (uint32_t)((lane & 15) * ASTR + ((lane >> 4) << 3)) * 2;
    const uint32_t boff = (uint32_t)(((lane & 7) + ((lane >> 4) << 3)) * ASTR +
                                     (((lane >> 3) & 1) << 3)) * 2;

    float acc[12][4] = {};
    float4 xr[4];

    auto ldx = [&](float4* r, int chunk) {
#pragma unroll
        for (int i = 0; i < 4; i++) {
            int idx = tid + i * 256;
            int row = idx >> 4, c = (idx & 15) * 4;
            r[i] = *(const float4*)(x + (size_t)(rowBase + row) * C + chunk * 64 + c);
        }
    };
    auto stx = [&](const float4* r, int buf) {
        char* st = sc + buf * (STG * 2);
#pragma unroll
        for (int i = 0; i < 4; i++) {
            int idx = tid + i * 256;
            int row = idx >> 4, c = (idx & 15) * 4;
            const float a[4] = {r[i].x, r[i].y, r[i].z, r[i].w};
            __nv_bfloat16 h[4], l[4];
#pragma unroll
            for (int u = 0; u < 4; u++) split1(a[u], h[u], l[u]);
            const uint32_t d = (uint32_t)(row * ASTR + c) * 2;
            *(uint32_t*)(st + AH_E * 2 + d)     = bf2pack(h[0], h[1]);
            *(uint32_t*)(st + AH_E * 2 + d + 4) = bf2pack(h[2], h[3]);
            *(uint32_t*)(st + AL_E * 2 + d)     = bf2pack(l[0], l[1]);
            *(uint32_t*)(st + AL_E * 2 + d + 4) = bf2pack(l[2], l[3]);
        }
    };
    auto ldw = [&](int buf, int chunk) {
        const uint32_t sb = su + (uint32_t)buf * (STG * 2);
        const int k0 = chunk * 64;
#pragma unroll
        for (int i = 0; i < 6; i++) {
            int idx = tid + i * 256;
            int row = idx >> 3, c = (idx & 7) * 8;   // 192 rows x 8 cp16
            const size_t gs = (size_t)row * C + k0 + c;
            const uint32_t d = (uint32_t)(row * ASTR + c) * 2;
            cp16(sb + BH_E * 2 + d, g_wh + gs);
            cp16(sb + BL_E * 2 + d, g_wl + gs);
        }
        CP_COMMIT();
    };
    auto compute = [&](int buf) {
        const uint32_t sb = su + (uint32_t)buf * (STG * 2);
#pragma unroll
        for (int kf = 0; kf < 4; kf++) {
            uint32_t ah[4], al[4];
            const uint32_t abase =
                sb + (uint32_t)((wm * 16) * ASTR + kf * 16) * 2 + aoff;
            ldsm4(ah, abase + AH_E * 2);
            ldsm4(al, abase + AL_E * 2);
#pragma unroll
            for (int n2 = 0; n2 < 6; n2++) {
                uint32_t bh[4], bl[4];
                const uint32_t bbase =
                    sb + (uint32_t)((wn * 96 + n2 * 16) * ASTR + kf * 16) * 2 + boff;
                ldsm4(bh, bbase + BH_E * 2);
                ldsm4(bl, bbase + BL_E * 2);
#pragma unroll
                for (int h2 = 0; h2 < 2; h2++) {
                    float* d = acc[n2 * 2 + h2];
                    mma_bf16(d, ah, bh + h2 * 2);   // hi*hi
                    mma_bf16(d, ah, bl + h2 * 2);   // hi*lo
                    mma_bf16(d, al, bh + h2 * 2);   // lo*hi
                }
            }
        }
    };

    // prologue: chunks 0,1
    ldx(xr, 0); stx(xr, 0);
    ldx(xr, 1); stx(xr, 1);
    ldw(0, 0);
    ldw(1, 1);

    for (int j = 0; j < 16; j++) {
        if (j + 2 < 16) ldx(xr, j + 2);          // LDG early, hidden under MMA
        if (j < 14) CP_WAIT1(); else CP_WAIT0();
        __syncthreads();
        compute(j & 1);
        __syncthreads();
        if (j + 2 < 16) { stx(xr, j & 1); ldw(j & 1, j + 2); }
    }

    // epilogue: split fp32 acc to bf16 hi/lo; route per weight (col/64)
    const int g2 = lane >> 2;
    const int t2 = (lane & 3) * 2;
#pragma unroll
    for (int nf = 0; nf < 12; nf++) {
        const int colg = wn * 96 + nf * 8 + t2;
        const int w = colg >> 6;
        const int c = colg & 63;
        const size_t row0 = rowBase + wm * 16 + g2;
        __nv_bfloat16 h[4], l[4];
        if (w < 2) {
            __nv_bfloat16* dh = w ? g_kh : g_qh;
            __nv_bfloat16* dl = w ? g_kl : g_ql;
            const float s = w ? 1.0f : QSCALE;
#pragma unroll
            for (int u = 0; u < 4; u++) split1(acc[nf][u] * s, h[u], l[u]);
            *(__nv_bfloat162*)(dh + row0 * H + c)       = {h[0], h[1]};
            *(__nv_bfloat162*)(dl + row0 * H + c)       = {l[0], l[1]};
            *(__nv_bfloat162*)(dh + (row0 + 8) * H + c) = {h[2], h[3]};
            *(__nv_bfloat162*)(dl + (row0 + 8) * H + c) = {l[2], l[3]};
        } else {
#pragma unroll
            for (int u = 0; u < 4; u++) split1(acc[nf][u], h[u], l[u]);
            g_vth[(size_t)c * NROW + row0]           = h[0];
            g_vth[(size_t)(c + 1) * NROW + row0]     = h[1];
            g_vth[(size_t)c * NROW + row0 + 8]       = h[2];
            g_vth[(size_t)(c + 1) * NROW + row0 + 8] = h[3];
            g_vtl[(size_t)c * NROW + row0]           = l[0];
            g_vtl[(size_t)(c + 1) * NROW + row0]     = l[1];
            g_vtl[(size_t)c * NROW + row0 + 8]       = l[2];
            g_vtl[(size_t)(c + 1) * NROW + row0 + 8] = l[3];
        }
    }
}

// ---------------------------------------------------------------------------
// Kernel 2: causal flash attention on HMMA, split-K over the key range.
// grid = 256 CTAs (32 q-tiles x 2 splits x 4 batches), decoded longest-first
// with a fold so bid%148 SM placement pairs long CTAs with short ones.
// Each CTA writes unnormalized partials (o_raw, m, l); combine() merges.
// ---------------------------------------------------------------------------
#define AT_STR 72
#define QH_E 0
#define QL_E 4608
#define STG_E(b) (9216 + (b) * 18432)
#define KH_E 0
#define KL_E 4608
#define VH_E 9216
#define VL_E 13824
#define ATT_SMEM (46080 * 2)   // 92160 bytes

__global__ __launch_bounds__(128, 2) void attn_mma() {
    extern __shared__ __nv_bfloat16 smb[];
    const uint32_t su = smem_u32(smb);
    const int tid = threadIdx.x;
    const int lane = tid & 31;
    const int wid = tid >> 5;

    // job decode: global longest-first; fold second wave short-end-first
    const int idx = blockIdx.x;
    const int job = (idx < 148) ? idx : (403 - idx);
    const int qt  = 31 - (job >> 3);
    const int sub = job & 7;
    const int s   = sub & 1;
    const int bT  = (sub >> 1) * T;
    const int qBase = qt * 64;

    const int n_tiles = qt + 1;
    const int h1 = (n_tiles + 1) >> 1;
    const int start = s ? h1 : 0;
    const int end   = s ? n_tiles : h1;

    if (start >= end) {   // empty split (qt==0, s==1): write identity partial
        for (int i = tid; i < 64 * 16; i += 128) {
            int row = i >> 4, c4 = i & 15;
            *(float4*)(g_po + ((size_t)s * NROW + bT + qBase + row) * H + c4 * 4) =
                make_float4(0.f, 0.f, 0.f, 0.f);
        }
        if (tid < 64) {
            size_t pr = (size_t)s * NROW + bT + qBase + tid;
            g_pm[pr] = -1e30f;
            g_pl[pr] = 0.f;
        }
        return;
    }

    const int g2 = lane >> 2;
    const int t2 = (lane & 3) * 2;
    const uint32_t aoff = (uint32_t)((lane & 15) * AT_STR + ((lane >> 4) << 3)) * 2;
    const uint32_t boff = (uint32_t)(((lane & 7) + ((lane >> 4) << 3)) * AT_STR +
                                     (((lane >> 3) & 1) << 3)) * 2;

    auto load_q = [&]() {
#pragma unroll
        for (int i = 0; i < 4; i++) {
            int idx2 = tid + i * 128;
            int row = idx2 >> 3, c = (idx2 & 7) * 8;
            const size_t gs = (size_t)(bT + qBase + row) * H + c;
            const uint32_t d = (uint32_t)(row * AT_STR + c) * 2;
            cp16(su + QH_E * 2 + d, g_qh + gs);
            cp16(su + QL_E * 2 + d, g_ql + gs);
        }
    };
    auto load_kv = [&](int buf, int j) {
        const uint32_t sb = su + STG_E(buf) * 2;
        const int kb = j * 64;
#pragma unroll
        for (int i = 0; i < 4; i++) {
            int idx2 = tid + i * 128;
            int row = idx2 >> 3, c = (idx2 & 7) * 8;
            const uint32_t d = (uint32_t)(row * AT_STR + c) * 2;
            const size_t gk = (size_t)(bT + kb + row) * H + c;
            cp16(sb + KH_E * 2 + d, g_kh + gk);
            cp16(sb + KL_E * 2 + d, g_kl + gk);
            const size_t gv = (size_t)row * NROW + bT + kb + c;   // row = h
            cp16(sb + VH_E * 2 + d, g_vth + gv);
            cp16(sb + VL_E * 2 + d, g_vtl + gv);
        }
        CP_COMMIT();
    };

    load_q();
    load_kv(0, start);
    CP_COMMIT();
    if (start + 1 < end) load_kv(1, start + 1);

    uint32_t qfh[4][4], qfl[4][4];
    float o[8][4] = {};
    float m0 = -1e30f, m1 = -1e30f, l0 = 0.0f, l1 = 0.0f;
    const int r0loc = 16 * wid + g2;

    for (int j = start; j < end; j++) {
        if (j < end - 1) CP_WAIT1(); else CP_WAIT0();
        __syncthreads();

        if (j == start) {
#pragma unroll
            for (int kf = 0; kf < 4; kf++) {
                const uint32_t base =
                    (uint32_t)((16 * wid) * AT_STR + kf * 16) * 2 + aoff;
                ldsm4(qfh[kf], su + QH_E * 2 + base);
                ldsm4(qfl[kf], su + QL_E * 2 + base);
            }
        }

        const uint32_t sb = su + STG_E((j - start) & 1) * 2;

        // ---- S = Q K^T ----
        float sa[8][4] = {};
#pragma unroll
        for (int kf = 0; kf < 4; kf++) {
            uint32_t bh[16], bl[16];
#pragma unroll
            for (int n2 = 0; n2 < 4; n2++) {
                const uint32_t base =
                    (uint32_t)((n2 * 16) * AT_STR + kf * 16) * 2 + boff;
                ldsm4(bh + n2 * 4, sb + KH_E * 2 + base);
                ldsm4(bl + n2 * 4, sb + KL_E * 2 + base);
            }
#pragma unroll
            for (int nf = 0; nf < 8; nf++) {
                mma_bf16(sa[nf], qfh[kf], bh + nf * 2);
                mma_bf16(sa[nf], qfh[kf], bl + nf * 2);
                mma_bf16(sa[nf], qfl[kf], bh + nf * 2);
            }
        }

        // ---- causal mask (diag tile only; kBase == qBase there) ----
        if (j == qt) {
#pragma unroll
            for (int nf = 0; nf < 8; nf++) {
                const int n0 = nf * 8 + t2;
                if (n0     > r0loc)     sa[nf][0] = -1e30f;
                if (n0 + 1 > r0loc)     sa[nf][1] = -1e30f;
                if (n0     > r0loc + 8) sa[nf][2] = -1e30f;
                if (n0 + 1 > r0loc + 8) sa[nf][3] = -1e30f;
            }
        }

        // ---- online softmax (log2 domain; QSCALE folded into Q) ----
        float mx0 = -1e30f, mx1 = -1e30f;
#pragma unroll
        for (int nf = 0; nf < 8; nf++) {
            mx0 = fmaxf(mx0, fmaxf(sa[nf][0], sa[nf][1]));
            mx1 = fmaxf(mx1, fmaxf(sa[nf][2], sa[nf][3]));
        }
        mx0 = fmaxf(mx0, __shfl_xor_sync(0xffffffffu, mx0, 1));
        mx0 = fmaxf(mx0, __shfl_xor_sync(0xffffffffu, mx0, 2));
        mx1 = fmaxf(mx1, __shfl_xor_sync(0xffffffffu, mx1, 1));
        mx1 = fmaxf(mx1, __shfl_xor_sync(0xffffffffu, mx1, 2));
        const float mn0 = fmaxf(m0, mx0);
        const float mn1 = fmaxf(m1, mx1);
        const float corr0 = exp2f(m0 - mn0);
        const float corr1 = exp2f(m1 - mn1);

        uint32_t pah[4][4], pal[4][4];
        float rs0 = 0.0f, rs1 = 0.0f;
#pragma unroll
        for (int nf = 0; nf < 8; nf++) {
            const float p0 = exp2f(sa[nf][0] - mn0);
            const float p1 = exp2f(sa[nf][1] - mn0);
            const float p2 = exp2f(sa[nf][2] - mn1);
            const float p3 = exp2f(sa[nf][3] - mn1);
            rs0 += p0 + p1;
            rs1 += p2 + p3;
            __nv_bfloat16 h0, h1, h2, h3, lo0, lo1, lo2, lo3;
            split1(p0, h0, lo0); split1(p1, h1, lo1);
            split1(p2, h2, lo2); split1(p3, h3, lo3);
            const int kf = nf >> 1;
            const int rb = (nf & 1) * 2;
            pah[kf][rb]     = bf2pack(h0, h1);
            pah[kf][rb + 1] = bf2pack(h2, h3);
            pal[kf][rb]     = bf2pack(lo0, lo1);
            pal[kf][rb + 1] = bf2pack(lo2, lo3);
        }
        rs0 += __shfl_xor_sync(0xffffffffu, rs0, 1);
        rs0 += __shfl_xor_sync(0xffffffffu, rs0, 2);
        rs1 += __shfl_xor_sync(0xffffffffu, rs1, 1);
        rs1 += __shfl_xor_sync(0xffffffffu, rs1, 2);
        l0 = l0 * corr0 + rs0;
        l1 = l1 * corr1 + rs1;
        m0 = mn0;
        m1 = mn1;
#pragma unroll
        for (int hf = 0; hf < 8; hf++) {
            o[hf][0] *= corr0; o[hf][1] *= corr0;
            o[hf][2] *= corr1; o[hf][3] *= corr1;
        }

        // ---- O += P Vt^T ----
#pragma unroll
        for (int kf = 0; kf < 4; kf++) {
            uint32_t vh[16], vl[16];
#pragma unroll
            for (int n2 = 0; n2 < 4; n2++) {
                const uint32_t base =
                    (uint32_t)((n2 * 16) * AT_STR + kf * 16) * 2 + boff;
                ldsm4(vh + n2 * 4, sb + VH_E * 2 + base);
                ldsm4(vl + n2 * 4, sb + VL_E * 2 + base);
            }
#pragma unroll
            for (int hf = 0; hf < 8; hf++) {
                mma_bf16(o[hf], pah[kf], vh + hf * 2);
                mma_bf16(o[hf], pah[kf], vl + hf * 2);
                mma_bf16(o[hf], pal[kf], vh + hf * 2);
            }
        }

        if (j + 2 < end) {
            __syncthreads();
            load_kv((j - start) & 1, j + 2);
        }
    }

    // ---- epilogue: unnormalized partials + stats ----
    const size_t row0 = (size_t)s * NROW + bT + qBase + 16 * wid + g2;
#pragma unroll
    for (int hf = 0; hf < 8; hf++) {
        const int col = hf * 8 + t2;
        *(float2*)(g_po + row0 * H + col)       = {o[hf][0], o[hf][1]};
        *(float2*)(g_po + (row0 + 8) * H + col) = {o[hf][2], o[hf][3]};
    }
    if ((lane & 3) == 0) {
        g_pm[row0]     = m0;  g_pl[row0]     = l0;
        g_pm[row0 + 8] = m1;  g_pl[row0 + 8] = l1;
    }
}

// ---------------------------------------------------------------------------
// Kernel 3: merge the two split-K partials into the final output.
// ---------------------------------------------------------------------------
__global__ __launch_bounds__(256) void combine(float* __restrict__ out) {
    const int idx = blockIdx.x * 256 + threadIdx.x;   // NROW*16 = 131072
    const int row = idx >> 4, c4 = idx & 15;
    const float m0 = g_pm[row], m1 = g_pm[NROW + row];
    const float l0 = g_pl[row], l1 = g_pl[NROW + row];
    const float M = fmaxf(m0, m1);
    float w0 = exp2f(m0 - M), w1 = exp2f(m1 - M);
    const float inv = 1.0f / (l0 * w0 + l1 * w1);
    w0 *= inv; w1 *= inv;
    const float4 a = *(const float4*)(g_po + (size_t)row * H + c4 * 4);
    const float4 b = *(const float4*)(g_po + (size_t)(NROW + row) * H + c4 * 4);
    float4 o = {a.x * w0 + b.x * w1, a.y * w0 + b.y * w1,
                a.z * w0 + b.z * w1, a.w * w0 + b.w * w1};
    *(float4*)(out + (size_t)row * H + c4 * 4) = o;
}

extern "C" void kernel_launch(void* const* d_in, const int* in_sizes, int n_in,
                              void* d_out, int out_size) {
    const float* x  = (const float*)d_in[0];
    const float* Wq = (const float*)d_in[1];
    const float* Wk = (const float*)d_in[2];
    const float* Wv = (const float*)d_in[3];
    float* out = (float*)d_out;

    cudaFuncSetAttribute(qkv_mma, cudaFuncAttributeMaxDynamicSharedMemorySize,
                         PROJ_SMEM);
    cudaFuncSetAttribute(attn_mma, cudaFuncAttributeMaxDynamicSharedMemorySize,
                         ATT_SMEM);

    convert_w<<<W4 / 256, 256>>>(Wq, Wk, Wv);
    qkv_mma<<<128, 256, PROJ_SMEM>>>(x);
    attn_mma<<<256, 128, ATT_SMEM>>>();
    combine<<<NROW * 16 / 256, 256>>>(out);
}

// round 14
// speedup vs baseline: 1.0035x; 1.0035x over previous
#include <cuda_runtime.h>
#include <cuda_bf16.h>
#include <cstdint>
#include <cstddef>

#define B 4
#define T 2048
#define C 1024
#define H 64
#define NROW (B * T)
#define QSCALE 0.18033688011112042f   // 0.125 * log2(e)

// pre-split W (hi/lo bf16): rows 0-63 Wq, 64-127 Wk, 128-191 Wv
__device__ __align__(16) __nv_bfloat16 g_wh[192 * C];
__device__ __align__(16) __nv_bfloat16 g_wl[192 * C];
// projected q/k (bf16 hi/lo, [row][h]; q pre-scaled) and transposed v ([h][row])
__device__ __align__(16) __nv_bfloat16 g_qh[NROW * H];
__device__ __align__(16) __nv_bfloat16 g_ql[NROW * H];
__device__ __align__(16) __nv_bfloat16 g_kh[NROW * H];
__device__ __align__(16) __nv_bfloat16 g_kl[NROW * H];
__device__ __align__(16) __nv_bfloat16 g_vth[H * NROW];
__device__ __align__(16) __nv_bfloat16 g_vtl[H * NROW];
// split-K attention partials: [split][row][...]
__device__ float g_po[2 * NROW * H];
__device__ float g_pm[2 * NROW];
__device__ float g_pl[2 * NROW];

// ---------------------------------------------------------------------------
// Baseline-PTX helpers (sm_80+ only — no tcgen05 on this toolchain)
// ---------------------------------------------------------------------------
__device__ __forceinline__ uint32_t smem_u32(const void* p) {
    uint32_t a;
    asm("{ .reg .u64 t; cvta.to.shared.u64 t, %1; cvt.u32.u64 %0, t; }"
        : "=r"(a) : "l"(p));
    return a;
}
__device__ __forceinline__ void cp16(uint32_t dst, const void* src) {
    asm volatile("cp.async.cg.shared.global [%0], [%1], 16;"
                 :: "r"(dst), "l"(src) : "memory");
}
#define CP_COMMIT() asm volatile("cp.async.commit_group;" ::: "memory")
#define CP_WAIT1()  asm volatile("cp.async.wait_group 1;" ::: "memory")
#define CP_WAIT0()  asm volatile("cp.async.wait_group 0;" ::: "memory")
__device__ __forceinline__ void ldsm4(uint32_t* r, uint32_t addr) {
    asm volatile("ldmatrix.sync.aligned.m8n8.x4.shared.b16 {%0,%1,%2,%3}, [%4];"
                 : "=r"(r[0]), "=r"(r[1]), "=r"(r[2]), "=r"(r[3]) : "r"(addr));
}
__device__ __forceinline__ void mma_bf16(float* d, const uint32_t* a,
                                         const uint32_t* b) {
    asm volatile(
        "mma.sync.aligned.m16n8k16.row.col.f32.bf16.bf16.f32 "
        "{%0,%1,%2,%3}, {%4,%5,%6,%7}, {%8,%9}, {%0,%1,%2,%3};"
        : "+f"(d[0]), "+f"(d[1]), "+f"(d[2]), "+f"(d[3])
        : "r"(a[0]), "r"(a[1]), "r"(a[2]), "r"(a[3]), "r"(b[0]), "r"(b[1]));
}
__device__ __forceinline__ void split1(float v, __nv_bfloat16& h, __nv_bfloat16& l) {
    h = __float2bfloat16(v);
    l = __float2bfloat16(v - __bfloat162float(h));
}
__device__ __forceinline__ uint32_t bf2pack(__nv_bfloat16 lo, __nv_bfloat16 hi) {
    __nv_bfloat162 t{lo, hi};
    return *reinterpret_cast<uint32_t*>(&t);
}

// ---------------------------------------------------------------------------
// Kernel 0: split packed W into bf16 hi/lo (x is split inline in qkv_mma now)
// ---------------------------------------------------------------------------
#define W4 (192 * C / 4)

__global__ __launch_bounds__(256) void convert_w(const float* __restrict__ Wq,
                                                 const float* __restrict__ Wk,
                                                 const float* __restrict__ Wv) {
    int i = blockIdx.x * 256 + threadIdx.x;
    if (i >= W4) return;
    int wrow = i >> 8;            // 0..191
    int c4 = i & 255;
    const float* src = (wrow < 64)  ? Wq + (size_t)wrow * C
                     : (wrow < 128) ? Wk + (size_t)(wrow - 64) * C
                                    : Wv + (size_t)(wrow - 128) * C;
    float4 v = ((const float4*)src)[c4];
    const float a[4] = {v.x, v.y, v.z, v.w};
    __nv_bfloat16 h[4], l[4];
#pragma unroll
    for (int j = 0; j < 4; j++) split1(a[j], h[j], l[j]);
    size_t off = (size_t)wrow * C + (size_t)c4 * 4;
    __nv_bfloat162* ph = (__nv_bfloat162*)(g_wh + off);
    __nv_bfloat162* pl = (__nv_bfloat162*)(g_wl + off);
    ph[0] = {h[0], h[1]}; ph[1] = {h[2], h[3]};
    pl[0] = {l[0], l[1]}; pl[1] = {l[2], l[3]};
}

// ---------------------------------------------------------------------------
// Kernel 1: QKV projection on HMMA, fused x split.
// grid = 128 CTAs (M-tiles of 64 rows), N=192 (q|k|v), 256 threads = 8 warps
// (4m x 2n; warp tile m16 x n96). K chunks of 64, double-buffered:
// x fp32 via LDG -> in-register hi/lo split -> STS; W hi/lo via cp.async.
// ---------------------------------------------------------------------------
#define ASTR 72
#define AH_E 0
#define AL_E 4608          // 64*72
#define BH_E 9216
#define BL_E 23040         // +192*72
#define STG 36864          // bf16 elems per stage
#define PROJ_SMEM (2 * STG * 2)   // 147456 bytes

__global__ __launch_bounds__(256, 1) void qkv_mma(const float* __restrict__ x) {
    extern __shared__ __nv_bfloat16 smb[];
    char* sc = (char*)smb;
    const uint32_t su = smem_u32(smb);
    const int tid = threadIdx.x;
    const int lane = tid & 31;
    const int wid = tid >> 5;
    const int wm = wid & 3;        // m block: rows wm*16..wm*16+15
    const int wn = wid >> 2;       // n block: cols wn*96..wn*96+95
    const int rowBase = blockIdx.x * 64;

    const uint32_t aoff = (uint32_t)((lane & 15) * ASTR + ((lane >> 4) << 3)) * 2;
    const uint32_t boff = (uint32_t)(((lane & 7) + ((lane >> 4) << 3)) * ASTR +
                                     (((lane >> 3) & 1) << 3)) * 2;

    float acc[12][4] = {};
    float4 xr[4];

    auto ldx = [&](float4* r, int chunk) {
#pragma unroll
        for (int i = 0; i < 4; i++) {
            int idx = tid + i * 256;
            int row = idx >> 4, c = (idx & 15) * 4;
            r[i] = *(const float4*)(x + (size_t)(rowBase + row) * C + chunk * 64 + c);
        }
    };
    auto stx = [&](const float4* r, int buf) {
        char* st = sc + buf * (STG * 2);
#pragma unroll
        for (int i = 0; i < 4; i++) {
            int idx = tid + i * 256;
            int row = idx >> 4, c = (idx & 15) * 4;
            const float a[4] = {r[i].x, r[i].y, r[i].z, r[i].w};
            __nv_bfloat16 h[4], l[4];
#pragma unroll
            for (int u = 0; u < 4; u++) split1(a[u], h[u], l[u]);
            const uint32_t d = (uint32_t)(row * ASTR + c) * 2;
            *(uint32_t*)(st + AH_E * 2 + d)     = bf2pack(h[0], h[1]);
            *(uint32_t*)(st + AH_E * 2 + d + 4) = bf2pack(h[2], h[3]);
            *(uint32_t*)(st + AL_E * 2 + d)     = bf2pack(l[0], l[1]);
            *(uint32_t*)(st + AL_E * 2 + d + 4) = bf2pack(l[2], l[3]);
        }
    };
    auto ldw = [&](int buf, int chunk) {
        const uint32_t sb = su + (uint32_t)buf * (STG * 2);
        const int k0 = chunk * 64;
#pragma unroll
        for (int i = 0; i < 6; i++) {
            int idx = tid + i * 256;
            int row = idx >> 3, c = (idx & 7) * 8;   // 192 rows x 8 cp16
            const size_t gs = (size_t)row * C + k0 + c;
            const uint32_t d = (uint32_t)(row * ASTR + c) * 2;
            cp16(sb + BH_E * 2 + d, g_wh + gs);
            cp16(sb + BL_E * 2 + d, g_wl + gs);
        }
        CP_COMMIT();
    };
    auto compute = [&](int buf) {
        const uint32_t sb = su + (uint32_t)buf * (STG * 2);
#pragma unroll
        for (int kf = 0; kf < 4; kf++) {
            uint32_t ah[4], al[4];
            const uint32_t abase =
                sb + (uint32_t)((wm * 16) * ASTR + kf * 16) * 2 + aoff;
            ldsm4(ah, abase + AH_E * 2);
            ldsm4(al, abase + AL_E * 2);
#pragma unroll
            for (int n2 = 0; n2 < 6; n2++) {
                uint32_t bh[4], bl[4];
                const uint32_t bbase =
                    sb + (uint32_t)((wn * 96 + n2 * 16) * ASTR + kf * 16) * 2 + boff;
                ldsm4(bh, bbase + BH_E * 2);
                ldsm4(bl, bbase + BL_E * 2);
#pragma unroll
                for (int h2 = 0; h2 < 2; h2++) {
                    float* d = acc[n2 * 2 + h2];
                    mma_bf16(d, ah, bh + h2 * 2);   // hi*hi
                    mma_bf16(d, ah, bl + h2 * 2);   // hi*lo
                    mma_bf16(d, al, bh + h2 * 2);   // lo*hi
                }
            }
        }
    };

    // prologue: chunks 0,1
    ldx(xr, 0); stx(xr, 0);
    ldx(xr, 1); stx(xr, 1);
    ldw(0, 0);
    ldw(1, 1);

    for (int j = 0; j < 16; j++) {
        if (j + 2 < 16) ldx(xr, j + 2);          // LDG early, hidden under MMA
        if (j < 14) CP_WAIT1(); else CP_WAIT0();
        __syncthreads();
        compute(j & 1);
        __syncthreads();
        if (j + 2 < 16) { stx(xr, j & 1); ldw(j & 1, j + 2); }
    }

    // epilogue: split fp32 acc to bf16 hi/lo; route per weight (col/64)
    const int g2 = lane >> 2;
    const int t2 = (lane & 3) * 2;
#pragma unroll
    for (int nf = 0; nf < 12; nf++) {
        const int colg = wn * 96 + nf * 8 + t2;
        const int w = colg >> 6;
        const int c = colg & 63;
        const size_t row0 = rowBase + wm * 16 + g2;
        __nv_bfloat16 h[4], l[4];
        if (w < 2) {
            __nv_bfloat16* dh = w ? g_kh : g_qh;
            __nv_bfloat16* dl = w ? g_kl : g_ql;
            const float s = w ? 1.0f : QSCALE;
#pragma unroll
            for (int u = 0; u < 4; u++) split1(acc[nf][u] * s, h[u], l[u]);
            *(__nv_bfloat162*)(dh + row0 * H + c)       = {h[0], h[1]};
            *(__nv_bfloat162*)(dl + row0 * H + c)       = {l[0], l[1]};
            *(__nv_bfloat162*)(dh + (row0 + 8) * H + c) = {h[2], h[3]};
            *(__nv_bfloat162*)(dl + (row0 + 8) * H + c) = {l[2], l[3]};
        } else {
#pragma unroll
            for (int u = 0; u < 4; u++) split1(acc[nf][u], h[u], l[u]);
            g_vth[(size_t)c * NROW + row0]           = h[0];
            g_vth[(size_t)(c + 1) * NROW + row0]     = h[1];
            g_vth[(size_t)c * NROW + row0 + 8]       = h[2];
            g_vth[(size_t)(c + 1) * NROW + row0 + 8] = h[3];
            g_vtl[(size_t)c * NROW + row0]           = l[0];
            g_vtl[(size_t)(c + 1) * NROW + row0]     = l[1];
            g_vtl[(size_t)c * NROW + row0 + 8]       = l[2];
            g_vtl[(size_t)(c + 1) * NROW + row0 + 8] = l[3];
        }
    }
}

// ---------------------------------------------------------------------------
// Kernel 2: causal flash attention on HMMA, split-K over the key range.
// grid = 256 CTAs (32 q-tiles x 2 splits x 4 batches), decoded longest-first
// with a fold so bid%148 SM placement pairs long CTAs with short ones.
// Each CTA writes unnormalized partials (o_raw, m, l); combine() merges.
// ---------------------------------------------------------------------------
#define AT_STR 72
#define QH_E 0
#define QL_E 4608
#define STG_E(b) (9216 + (b) * 18432)
#define KH_E 0
#define KL_E 4608
#define VH_E 9216
#define VL_E 13824
#define ATT_SMEM (46080 * 2)   // 92160 bytes

__global__ __launch_bounds__(128, 2) void attn_mma() {
    extern __shared__ __nv_bfloat16 smb[];
    const uint32_t su = smem_u32(smb);
    const int tid = threadIdx.x;
    const int lane = tid & 31;
    const int wid = tid >> 5;

    // job decode: global longest-first; fold second wave short-end-first
    const int idx = blockIdx.x;
    const int job = (idx < 148) ? idx : (403 - idx);
    const int qt  = 31 - (job >> 3);
    const int sub = job & 7;
    const int s   = sub & 1;
    const int bT  = (sub >> 1) * T;
    const int qBase = qt * 64;

    const int n_tiles = qt + 1;
    const int h1 = (n_tiles + 1) >> 1;
    const int start = s ? h1 : 0;
    const int end   = s ? n_tiles : h1;

    if (start >= end) {   // empty split (qt==0, s==1): write identity partial
        for (int i = tid; i < 64 * 16; i += 128) {
            int row = i >> 4, c4 = i & 15;
            *(float4*)(g_po + ((size_t)s * NROW + bT + qBase + row) * H + c4 * 4) =
                make_float4(0.f, 0.f, 0.f, 0.f);
        }
        if (tid < 64) {
            size_t pr = (size_t)s * NROW + bT + qBase + tid;
            g_pm[pr] = -1e30f;
            g_pl[pr] = 0.f;
        }
        return;
    }

    const int g2 = lane >> 2;
    const int t2 = (lane & 3) * 2;
    const uint32_t aoff = (uint32_t)((lane & 15) * AT_STR + ((lane >> 4) << 3)) * 2;
    const uint32_t boff = (uint32_t)(((lane & 7) + ((lane >> 4) << 3)) * AT_STR +
                                     (((lane >> 3) & 1) << 3)) * 2;

    auto load_q = [&]() {
#pragma unroll
        for (int i = 0; i < 4; i++) {
            int idx2 = tid + i * 128;
            int row = idx2 >> 3, c = (idx2 & 7) * 8;
            const size_t gs = (size_t)(bT + qBase + row) * H + c;
            const uint32_t d = (uint32_t)(row * AT_STR + c) * 2;
            cp16(su + QH_E * 2 + d, g_qh + gs);
            cp16(su + QL_E * 2 + d, g_ql + gs);
        }
    };
    auto load_kv = [&](int buf, int j) {
        const uint32_t sb = su + STG_E(buf) * 2;
        const int kb = j * 64;
#pragma unroll
        for (int i = 0; i < 4; i++) {
            int idx2 = tid + i * 128;
            int row = idx2 >> 3, c = (idx2 & 7) * 8;
            const uint32_t d = (uint32_t)(row * AT_STR + c) * 2;
            const size_t gk = (size_t)(bT + kb + row) * H + c;
            cp16(sb + KH_E * 2 + d, g_kh + gk);
            cp16(sb + KL_E * 2 + d, g_kl + gk);
            const size_t gv = (size_t)row * NROW + bT + kb + c;   // row = h
            cp16(sb + VH_E * 2 + d, g_vth + gv);
            cp16(sb + VL_E * 2 + d, g_vtl + gv);
        }
        CP_COMMIT();
    };

    load_q();
    load_kv(0, start);
    CP_COMMIT();
    if (start + 1 < end) load_kv(1, start + 1);

    uint32_t qfh[4][4], qfl[4][4];
    float o[8][4] = {};
    float m0 = -1e30f, m1 = -1e30f, l0 = 0.0f, l1 = 0.0f;
    const int r0loc = 16 * wid + g2;

    for (int j = start; j < end; j++) {
        if (j < end - 1) CP_WAIT1(); else CP_WAIT0();
        __syncthreads();

        if (j == start) {
#pragma unroll
            for (int kf = 0; kf < 4; kf++) {
                const uint32_t base =
                    (uint32_t)((16 * wid) * AT_STR + kf * 16) * 2 + aoff;
                ldsm4(qfh[kf], su + QH_E * 2 + base);
                ldsm4(qfl[kf], su + QL_E * 2 + base);
            }
        }

        const uint32_t sb = su + STG_E((j - start) & 1) * 2;

        // ---- S = Q K^T ----
        float sa[8][4] = {};
#pragma unroll
        for (int kf = 0; kf < 4; kf++) {
            uint32_t bh[16], bl[16];
#pragma unroll
            for (int n2 = 0; n2 < 4; n2++) {
                const uint32_t base =
                    (uint32_t)((n2 * 16) * AT_STR + kf * 16) * 2 + boff;
                ldsm4(bh + n2 * 4, sb + KH_E * 2 + base);
                ldsm4(bl + n2 * 4, sb + KL_E * 2 + base);
            }
#pragma unroll
            for (int nf = 0; nf < 8; nf++) {
                mma_bf16(sa[nf], qfh[kf], bh + nf * 2);
                mma_bf16(sa[nf], qfh[kf], bl + nf * 2);
                mma_bf16(sa[nf], qfl[kf], bh + nf * 2);
            }
        }

        // ---- causal mask (diag tile only; kBase == qBase there) ----
        if (j == qt) {
#pragma unroll
            for (int nf = 0; nf < 8; nf++) {
                const int n0 = nf * 8 + t2;
                if (n0     > r0loc)     sa[nf][0] = -1e30f;
                if (n0 + 1 > r0loc)     sa[nf][1] = -1e30f;
                if (n0     > r0loc + 8) sa[nf][2] = -1e30f;
                if (n0 + 1 > r0loc + 8) sa[nf][3] = -1e30f;
            }
        }

        // ---- online softmax (log2 domain; QSCALE folded into Q) ----
        float mx0 = -1e30f, mx1 = -1e30f;
#pragma unroll
        for (int nf = 0; nf < 8; nf++) {
            mx0 = fmaxf(mx0, fmaxf(sa[nf][0], sa[nf][1]));
            mx1 = fmaxf(mx1, fmaxf(sa[nf][2], sa[nf][3]));
        }
        mx0 = fmaxf(mx0, __shfl_xor_sync(0xffffffffu, mx0, 1));
        mx0 = fmaxf(mx0, __shfl_xor_sync(0xffffffffu, mx0, 2));
        mx1 = fmaxf(mx1, __shfl_xor_sync(0xffffffffu, mx1, 1));
        mx1 = fmaxf(mx1, __shfl_xor_sync(0xffffffffu, mx1, 2));
        const float mn0 = fmaxf(m0, mx0);
        const float mn1 = fmaxf(m1, mx1);
        const float corr0 = exp2f(m0 - mn0);
        const float corr1 = exp2f(m1 - mn1);

        uint32_t pah[4][4], pal[4][4];
        float rs0 = 0.0f, rs1 = 0.0f;
#pragma unroll
        for (int nf = 0; nf < 8; nf++) {
            const float p0 = exp2f(sa[nf][0] - mn0);
            const float p1 = exp2f(sa[nf][1] - mn0);
            const float p2 = exp2f(sa[nf][2] - mn1);
            const float p3 = exp2f(sa[nf][3] - mn1);
            rs0 += p0 + p1;
            rs1 += p2 + p3;
            __nv_bfloat16 h0, h1, h2, h3, lo0, lo1, lo2, lo3;
            split1(p0, h0, lo0); split1(p1, h1, lo1);
            split1(p2, h2, lo2); split1(p3, h3, lo3);
            const int kf = nf >> 1;
            const int rb = (nf & 1) * 2;
            pah[kf][rb]     = bf2pack(h0, h1);
            pah[kf][rb + 1] = bf2pack(h2, h3);
            pal[kf][rb]     = bf2pack(lo0, lo1);
            pal[kf][rb + 1] = bf2pack(lo2, lo3);
        }
        rs0 += __shfl_xor_sync(0xffffffffu, rs0, 1);
        rs0 += __shfl_xor_sync(0xffffffffu, rs0, 2);
        rs1 += __shfl_xor_sync(0xffffffffu, rs1, 1);
        rs1 += __shfl_xor_sync(0xffffffffu, rs1, 2);
        l0 = l0 * corr0 + rs0;
        l1 = l1 * corr1 + rs1;
        m0 = mn0;
        m1 = mn1;
#pragma unroll
        for (int hf = 0; hf < 8; hf++) {
            o[hf][0] *= corr0; o[hf][1] *= corr0;
            o[hf][2] *= corr1; o[hf][3] *= corr1;
        }

        // ---- O += P Vt^T ----
#pragma unroll
        for (int kf = 0; kf < 4; kf++) {
            uint32_t vh[16], vl[16];
#pragma unroll
            for (int n2 = 0; n2 < 4; n2++) {
                const uint32_t base =
                    (uint32_t)((n2 * 16) * AT_STR + kf * 16) * 2 + boff;
                ldsm4(vh + n2 * 4, sb + VH_E * 2 + base);
                ldsm4(vl + n2 * 4, sb + VL_E * 2 + base);
            }
#pragma unroll
            for (int hf = 0; hf < 8; hf++) {
                mma_bf16(o[hf], pah[kf], vh + hf * 2);
                mma_bf16(o[hf], pah[kf], vl + hf * 2);
                mma_bf16(o[hf], pal[kf], vh + hf * 2);
            }
        }

        if (j + 2 < end) {
            __syncthreads();
            load_kv((j - start) & 1, j + 2);
        }
    }

    // ---- epilogue: unnormalized partials + stats ----
    const size_t row0 = (size_t)s * NROW + bT + qBase + 16 * wid + g2;
#pragma unroll
    for (int hf = 0; hf < 8; hf++) {
        const int col = hf * 8 + t2;
        *(float2*)(g_po + row0 * H + col)       = {o[hf][0], o[hf][1]};
        *(float2*)(g_po + (row0 + 8) * H + col) = {o[hf][2], o[hf][3]};
    }
    if ((lane & 3) == 0) {
        g_pm[row0]     = m0;  g_pl[row0]     = l0;
        g_pm[row0 + 8] = m1;  g_pl[row0 + 8] = l1;
    }
}

// ---------------------------------------------------------------------------
// Kernel 3: merge the two split-K partials into the final output.
// ---------------------------------------------------------------------------
__global__ __launch_bounds__(256) void combine(float* __restrict__ out) {
    const int idx = blockIdx.x * 256 + threadIdx.x;   // NROW*16 = 131072
    const int row = idx >> 4, c4 = idx & 15;
    const float m0 = g_pm[row], m1 = g_pm[NROW + row];
    const float l0 = g_pl[row], l1 = g_pl[NROW + row];
    const float M = fmaxf(m0, m1);
    float w0 = exp2f(m0 - M), w1 = exp2f(m1 - M);
    const float inv = 1.0f / (l0 * w0 + l1 * w1);
    w0 *= inv; w1 *= inv;
    const float4 a = *(const float4*)(g_po + (size_t)row * H + c4 * 4);
    const float4 b = *(const float4*)(g_po + (size_t)(NROW + row) * H + c4 * 4);
    float4 o = {a.x * w0 + b.x * w1, a.y * w0 + b.y * w1,
                a.z * w0 + b.z * w1, a.w * w0 + b.w * w1};
    *(float4*)(out + (size_t)row * H + c4 * 4) = o;
}

extern "C" void kernel_launch(void* const* d_in, const int* in_sizes, int n_in,
                              void* d_out, int out_size) {
    const float* x  = (const float*)d_in[0];
    const float* Wq = (const float*)d_in[1];
    const float* Wk = (const float*)d_in[2];
    const float* Wv = (const float*)d_in[3];
    float* out = (float*)d_out;

    cudaFuncSetAttribute(qkv_mma, cudaFuncAttributeMaxDynamicSharedMemorySize,
                         PROJ_SMEM);
    cudaFuncSetAttribute(attn_mma, cudaFuncAttributeMaxDynamicSharedMemorySize,
                         ATT_SMEM);

    convert_w<<<W4 / 256, 256>>>(Wq, Wk, Wv);
    qkv_mma<<<128, 256, PROJ_SMEM>>>(x);
    attn_mma<<<256, 128, ATT_SMEM>>>();
    combine<<<NROW * 16 / 256, 256>>>(out);
}